// round 4
// baseline (speedup 1.0000x reference)
#include <cuda_runtime.h>

// 2-layer LSTM (H=50), T=65536 strictly-serial steps, one persistent CTA.
// R2's validated 3-barrier pipeline on an R1-style full-row register layout,
// sized so weights (79 u64 = 158 regs) + working set fit the 256-reg cap at
// 256 threads with real headroom (the R2/R3 spill failure mode).
//
//   P0 gates(t<200): q = bb2 + W_hh2 @ h2(s-1)            [overlaps P1]
//   P1 units       : err; gates1 = a1 + w7*err; cell1 -> h1(s)
//   BAR_A
//   P2 gates       : sg2 = q + W_ih2 @ h1(s)
//                    sg1p(s+1) = bb1 + W_ih1@x(s+1) + W_hh1 @ h1(s)
//   BAR_B
//   P3 units       : cell2 -> h2(s); y += wout*h2 (smem atomic); cache x7
//   BAR_C

#define HDIM     50
#define INP      8
#define CHUNK    1024
#define NTHREADS 256
#define UBASE    206

typedef unsigned long long u64;

__device__ __forceinline__ u64 pk2(float lo, float hi) {
    u64 r; asm("mov.b64 %0, {%1,%2};" : "=l"(r) : "f"(lo), "f"(hi)); return r;
}
__device__ __forceinline__ float2 upk2(u64 v) {
    float2 f; asm("mov.b64 {%0,%1}, %2;" : "=f"(f.x), "=f"(f.y) : "l"(v)); return f;
}
__device__ __forceinline__ u64 ffma2(u64 a, u64 b, u64 c) {
    u64 d; asm("fma.rn.f32x2 %0, %1, %2, %3;" : "=l"(d) : "l"(a), "l"(b), "l"(c)); return d;
}
__device__ __forceinline__ float tanha(float x) {
    float r; asm("tanh.approx.f32 %0, %1;" : "=f"(r) : "f"(x)); return r;
}
__device__ __forceinline__ float sig(float x) {
    return fmaf(tanha(0.5f * x), 0.5f, 0.5f);
}

__global__ __launch_bounds__(NTHREADS, 1)
void lstm_pipe2_kernel(const float* __restrict__ input_seq,
                       const float* __restrict__ W_ih1, const float* __restrict__ W_hh1,
                       const float* __restrict__ b_ih1, const float* __restrict__ b_hh1,
                       const float* __restrict__ W_ih2, const float* __restrict__ W_hh2,
                       const float* __restrict__ b_ih2, const float* __restrict__ b_hh2,
                       const float* __restrict__ W_out, const float* __restrict__ b_out,
                       float* __restrict__ out, int T)
{
    __shared__ __align__(16) float sh1[52];     // h1(s), [50..51] = 0
    __shared__ __align__(16) float sh2[52];     // h2(s), [50..51] = 0
    __shared__ __align__(16) float sg1p[200];   // gates1(s+1) partial (pre-err)
    __shared__ __align__(16) float sg2[200];    // gates2(s)
    __shared__ float sy[2];                     // ping-pong y accumulators
    __shared__ __align__(16) float xbuf[(CHUNK + 1) * INP];

    const int t = threadIdx.x;
    const bool gateT = (t < 200);
    const int row = gateT ? t : 0;
    const bool unitT = (t >= UBASE);
    const int u = unitT ? (t - UBASE) : 0;

    // ---- per-thread full-row weights, f32x2 packed (79 u64 = 158 regs)
    u64 wx[4], wh1[25], wi2[25], wh2[25];
    float bb1, bb2;
    {
        const float* r1 = W_ih1 + row * INP;
        wx[0] = pk2(r1[0], r1[1]);
        wx[1] = pk2(r1[2], r1[3]);
        wx[2] = pk2(r1[4], r1[5]);
        wx[3] = pk2(r1[6], 0.0f);              // err input handled by units
        const float* r2 = W_hh1 + row * HDIM;
        const float* r3 = W_ih2 + row * HDIM;
        const float* r4 = W_hh2 + row * HDIM;
        #pragma unroll
        for (int j = 0; j < 25; ++j) {
            wh1[j] = pk2(r2[2*j], r2[2*j+1]);
            wi2[j] = pk2(r3[2*j], r3[2*j+1]);
            wh2[j] = pk2(r4[2*j], r4[2*j+1]);
        }
        bb1 = b_ih1[row] + b_hh1[row];
        bb2 = b_ih2[row] + b_hh2[row];
    }
    // ---- unit-thread constants
    const float wi7_0 = W_ih1[(u +   0) * INP + 7];
    const float wi7_1 = W_ih1[(u +  50) * INP + 7];
    const float wi7_2 = W_ih1[(u + 100) * INP + 7];
    const float wi7_3 = W_ih1[(u + 150) * INP + 7];
    const float wout_u = W_out[u];
    const float bo = b_out[0];

    for (int i = t; i < 52; i += NTHREADS) { sh1[i] = 0.0f; sh2[i] = 0.0f; }
    if (t == 0) { sy[0] = bo; sy[1] = 0.0f; }  // sy[1] read as y(-1)=0 at s=0

    float c1 = 0.0f, c2 = 0.0f, err = 0.0f, x7prev = 0.0f;

    __syncthreads();

    #pragma unroll 1
    for (int s = 0; s < T; ++s) {
        const int lo = s & (CHUNK - 1);
        if (lo == 0) {
            // stage CHUNK+1 steps (slot CHUNK holds x(s+1) for the chunk's last step)
            const float4* src = (const float4*)(input_seq + (size_t)s * INP);
            float4* dst = (float4*)xbuf;
            int n4 = (CHUNK + 1) * 2;
            int rem4 = (T - s) * 2;
            if (rem4 < n4) n4 = rem4;
            for (int i = t; i < n4; i += NTHREADS) dst[i] = src[i];
            __syncthreads();
            if (s == 0) {
                // bootstrap: sg1p(0) = bb1 + W_ih1 @ x(0)  (h1(-1)=0, err=0)
                if (gateT) {
                    float4 xa = *(const float4*)(xbuf);
                    float4 xb = *(const float4*)(xbuf + 4);
                    u64 a0 = ffma2(wx[0], pk2(xa.x, xa.y), pk2(bb1, 0.0f));
                    u64 a1 = ffma2(wx[1], pk2(xa.z, xa.w), pk2(0.0f, 0.0f));
                    a0 = ffma2(wx[2], pk2(xb.x, xb.y), a0);
                    a1 = ffma2(wx[3], pk2(xb.z, 0.0f), a1);
                    float2 f0 = upk2(a0), f1 = upk2(a1);
                    sg1p[row] = (f0.x + f1.x) + (f0.y + f1.y);
                }
                __syncthreads();
            }
        }

        u64 q0, q1;   // gates2 accumulator, carried P0 -> P2 across BAR_A
        if (gateT) {
            // ---- P0: q = bb2 + W_hh2 @ h2(s-1)   (overlaps unit P1)
            q0 = pk2(bb2, 0.0f); q1 = pk2(0.0f, 0.0f);
            const float4* hv = (const float4*)sh2;
            #pragma unroll
            for (int j = 0; j < 12; ++j) {
                float4 h = hv[j];
                q0 = ffma2(wh2[2*j],     pk2(h.x, h.y), q0);
                q1 = ffma2(wh2[2*j + 1], pk2(h.z, h.w), q1);
            }
            q0 = ffma2(wh2[24], ((const u64*)sh2)[24], q0);
        }
        if (unitT) {
            // ---- P1: err update, gates1 finish, cell1 -> h1(s)
            float y = sy[(s + 1) & 1];            // y(s-1)
            err = 0.9f * err + 0.1f * (x7prev - y);
            float ga = sg1p[u]       + wi7_0 * err;
            float gb = sg1p[u +  50] + wi7_1 * err;
            float gc = sg1p[u + 100] + wi7_2 * err;
            float gd = sg1p[u + 150] + wi7_3 * err;
            float I = sig(ga), F = sig(gb), G = tanha(gc), O = sig(gd);
            c1 = F * c1 + I * G;
            sh1[u] = O * tanha(c1);
            if (u == 0 && s > 0) out[s - 1] = y;
        }
        __syncthreads();   // BAR_A: h1(s) ready

        if (gateT) {
            // ---- P2: finish gates2(s) and sg1p(s+1); sh1 loaded once for both
            u64 a0 = pk2(bb1, 0.0f), a1 = pk2(0.0f, 0.0f);
            const float4* hv = (const float4*)sh1;
            #pragma unroll
            for (int j = 0; j < 12; ++j) {
                float4 h = hv[j];
                u64 hl = pk2(h.x, h.y), hh = pk2(h.z, h.w);
                a0 = ffma2(wh1[2*j],     hl, a0);
                a1 = ffma2(wh1[2*j + 1], hh, a1);
                q0 = ffma2(wi2[2*j],     hl, q0);
                q1 = ffma2(wi2[2*j + 1], hh, q1);
            }
            u64 htail = ((const u64*)sh1)[24];
            a0 = ffma2(wh1[24], htail, a0);
            q0 = ffma2(wi2[24], htail, q0);
            const float* xn = &xbuf[(lo + 1) * INP];   // x(s+1)
            float4 xa = *(const float4*)(xn);
            float4 xb = *(const float4*)(xn + 4);
            a0 = ffma2(wx[0], pk2(xa.x, xa.y), a0);
            a1 = ffma2(wx[1], pk2(xa.z, xa.w), a1);
            a0 = ffma2(wx[2], pk2(xb.x, xb.y), a0);
            a1 = ffma2(wx[3], pk2(xb.z, 0.0f), a1);
            float2 f0 = upk2(a0), f1 = upk2(a1);
            sg1p[row] = (f0.x + f1.x) + (f0.y + f1.y);
            float2 g0 = upk2(q0), g1 = upk2(q1);
            sg2[row] = (g0.x + g1.x) + (g0.y + g1.y);
        } else if (t == 200) {
            sy[s & 1] = bo;   // reseed write slot (last read at P1 of step s-1)
        }
        __syncthreads();   // BAR_B: sg2 ready, sy write slot seeded

        if (unitT) {
            // ---- P3: cell2 -> h2(s); y contribution; cache x7(s)
            float ga = sg2[u], gb = sg2[u + 50], gc = sg2[u + 100], gd = sg2[u + 150];
            float I = sig(ga), F = sig(gb), G = tanha(gc), O = sig(gd);
            c2 = F * c2 + I * G;
            float h2v = O * tanha(c2);
            sh2[u] = h2v;
            atomicAdd(&sy[s & 1], wout_u * h2v);
            x7prev = xbuf[lo * INP + 7];
        }
        __syncthreads();   // BAR_C: h2(s), y(s), sg1p(s+1) ready
    }

    if (t == UBASE) out[T - 1] = sy[(T - 1) & 1];
}

extern "C" void kernel_launch(void* const* d_in, const int* in_sizes, int n_in,
                              void* d_out, int out_size) {
    const int T = in_sizes[0] / INP;
    lstm_pipe2_kernel<<<1, NTHREADS>>>(
        (const float*)d_in[0],
        (const float*)d_in[1], (const float*)d_in[2],
        (const float*)d_in[3], (const float*)d_in[4],
        (const float*)d_in[5], (const float*)d_in[6],
        (const float*)d_in[7], (const float*)d_in[8],
        (const float*)d_in[9], (const float*)d_in[10],
        (float*)d_out, T);
}

// round 5
// speedup vs baseline: 3.0896x; 3.0896x over previous
#include <cuda_runtime.h>

// 2-layer LSTM (H=50), T=65536 serial steps, one persistent CTA.
// R1's homogeneous structure (all warps active in every phase — the only
// design that scheduled well; role-specialized pipelines ran 3x slower) with:
//   - tanh.approx.f32 activations (1 MUFU vs expf+div)
//   - float4 LDS.128 for every h-vector read
//   - vectorized redundant y-dot, err folded into the S1 input dot
//   - 256 threads = 8 warps = exactly 2 warps per SMSP

#define HDIM     50
#define INP      8
#define CHUNK    1024
#define NTHREADS 256

typedef unsigned long long u64;

__device__ __forceinline__ u64 pk2(float lo, float hi) {
    u64 r; asm("mov.b64 %0, {%1,%2};" : "=l"(r) : "f"(lo), "f"(hi)); return r;
}
__device__ __forceinline__ float2 upk2(u64 v) {
    float2 f; asm("mov.b64 {%0,%1}, %2;" : "=f"(f.x), "=f"(f.y) : "l"(v)); return f;
}
__device__ __forceinline__ u64 ffma2(u64 a, u64 b, u64 c) {
    u64 d; asm("fma.rn.f32x2 %0, %1, %2, %3;" : "=l"(d) : "l"(a), "l"(b), "l"(c)); return d;
}
__device__ __forceinline__ float tanha(float x) {
    float r; asm("tanh.approx.f32 %0, %1;" : "=f"(r) : "f"(x)); return r;
}
__device__ __forceinline__ float sig(float x) {
    return fmaf(tanha(0.5f * x), 0.5f, 0.5f);
}

__global__ __launch_bounds__(NTHREADS, 1)
void lstm_r5_kernel(const float* __restrict__ input_seq,
                    const float* __restrict__ W_ih1, const float* __restrict__ W_hh1,
                    const float* __restrict__ b_ih1, const float* __restrict__ b_hh1,
                    const float* __restrict__ W_ih2, const float* __restrict__ W_hh2,
                    const float* __restrict__ b_ih2, const float* __restrict__ b_hh2,
                    const float* __restrict__ W_out, const float* __restrict__ b_out,
                    float* __restrict__ out, int T)
{
    __shared__ __align__(16) float sh1[52];    // h1, [50..51]=0
    __shared__ __align__(16) float sh2[52];    // h2, [50..51]=0
    __shared__ __align__(16) float sg[200];    // gate scratch (layer 1, then layer 2)
    __shared__ __align__(16) float swout[52];  // W_out padded
    __shared__ __align__(16) float xbuf[CHUNK * INP];

    const int t = threadIdx.x;
    const int w = t >> 5;
    const int l = t & 31;
    const bool gateT = (t < 200);
    const int row = gateT ? t : 0;
    // units on warps 0 and 2 (SMSP 0 / SMSP 2) to spread MUFU work
    const bool unitT = ((w == 0) | (w == 2)) & (l < 25);
    const int u = (w == 0) ? l : (25 + l);

    // ---- per-thread full-row weights (f32x2 packed; index 25 = zero pad)
    u64 wx[4], wh1[26], wi2[26], wh2[26];
    float bb1, bb2;
    {
        const float* r1 = W_ih1 + row * INP;
        wx[0] = pk2(r1[0], r1[1]);
        wx[1] = pk2(r1[2], r1[3]);
        wx[2] = pk2(r1[4], r1[5]);
        wx[3] = pk2(r1[6], r1[7]);             // (x6, err) partner
        const float* r2 = W_hh1 + row * HDIM;
        const float* r3 = W_ih2 + row * HDIM;
        const float* r4 = W_hh2 + row * HDIM;
        #pragma unroll
        for (int j = 0; j < 25; ++j) {
            wh1[j] = pk2(r2[2*j], r2[2*j+1]);
            wi2[j] = pk2(r3[2*j], r3[2*j+1]);
            wh2[j] = pk2(r4[2*j], r4[2*j+1]);
        }
        wh1[25] = 0ULL; wi2[25] = 0ULL; wh2[25] = 0ULL;
        bb1 = b_ih1[row] + b_hh1[row];
        bb2 = b_ih2[row] + b_hh2[row];
    }
    const float bo = b_out[0];
    if (t < 52) {
        swout[t] = (t < HDIM) ? W_out[t] : 0.0f;
        sh1[t] = 0.0f;
        sh2[t] = 0.0f;
    }

    float c1 = 0.0f, c2 = 0.0f, err = 0.0f;
    __syncthreads();

    #pragma unroll 1
    for (int s = 0; s < T; ++s) {
        const int lo = s & (CHUNK - 1);
        if (lo == 0) {
            __syncthreads();   // previous chunk's S5 readers done
            const float4* src = (const float4*)(input_seq + (size_t)s * INP);
            float4* dst = (float4*)xbuf;
            int n4 = CHUNK * 2;
            int rem4 = (T - s) * 2;
            if (rem4 < n4) n4 = rem4;
            for (int i = t; i < n4; i += NTHREADS) dst[i] = src[i];
            __syncthreads();
        }
        const float* x = &xbuf[lo * INP];

        // ---- S1: gates1 = bb1 + W_ih1 @ [x0..x6, err] + W_hh1 @ h1
        if (gateT) {
            float4 xa = *(const float4*)(x);
            float4 xb = *(const float4*)(x + 4);
            u64 a0 = ffma2(wx[0], pk2(xa.x, xa.y), pk2(bb1, 0.0f));
            u64 a1 = ffma2(wx[1], pk2(xa.z, xa.w), pk2(0.0f, 0.0f));
            a0 = ffma2(wx[2], pk2(xb.x, xb.y), a0);
            a1 = ffma2(wx[3], pk2(xb.z, err), a1);
            const float4* hv = (const float4*)sh1;
            #pragma unroll
            for (int j = 0; j < 13; ++j) {
                float4 h = hv[j];
                a0 = ffma2(wh1[2*j],     pk2(h.x, h.y), a0);
                a1 = ffma2(wh1[2*j + 1], pk2(h.z, h.w), a1);
            }
            float2 f0 = upk2(a0), f1 = upk2(a1);
            sg[row] = (f0.x + f1.x) + (f0.y + f1.y);
        }
        __syncthreads();

        // ---- S2: cell 1
        if (unitT) {
            float I = sig(sg[u]);
            float F = sig(sg[u + 50]);
            float G = tanha(sg[u + 100]);
            float O = sig(sg[u + 150]);
            c1 = F * c1 + I * G;
            sh1[u] = O * tanha(c1);
        }
        __syncthreads();

        // ---- S3: gates2 = bb2 + W_ih2 @ h1 + W_hh2 @ h2
        if (gateT) {
            u64 a0 = pk2(bb2, 0.0f), a1 = pk2(0.0f, 0.0f);
            u64 q0 = pk2(0.0f, 0.0f), q1 = pk2(0.0f, 0.0f);
            const float4* h1v = (const float4*)sh1;
            const float4* h2v = (const float4*)sh2;
            #pragma unroll
            for (int j = 0; j < 13; ++j) {
                float4 ha = h1v[j];
                float4 hb = h2v[j];
                a0 = ffma2(wi2[2*j],     pk2(ha.x, ha.y), a0);
                a1 = ffma2(wi2[2*j + 1], pk2(ha.z, ha.w), a1);
                q0 = ffma2(wh2[2*j],     pk2(hb.x, hb.y), q0);
                q1 = ffma2(wh2[2*j + 1], pk2(hb.z, hb.w), q1);
            }
            float2 f0 = upk2(a0), f1 = upk2(a1), f2 = upk2(q0), f3 = upk2(q1);
            sg[row] = ((f0.x + f1.x) + (f0.y + f1.y)) + ((f2.x + f3.x) + (f2.y + f3.y));
        }
        __syncthreads();

        // ---- S4: cell 2
        if (unitT) {
            float I = sig(sg[u]);
            float F = sig(sg[u + 50]);
            float G = tanha(sg[u + 100]);
            float O = sig(sg[u + 150]);
            c2 = F * c2 + I * G;
            sh2[u] = O * tanha(c2);
        }
        __syncthreads();

        // ---- S5: redundant y + err in every thread (no broadcast barrier)
        {
            const float4* hv = (const float4*)sh2;
            const float4* wv = (const float4*)swout;
            u64 y0 = pk2(0.0f, 0.0f), y1 = pk2(0.0f, 0.0f);
            #pragma unroll
            for (int j = 0; j < 13; ++j) {
                float4 h = hv[j];
                float4 wq = wv[j];
                y0 = ffma2(pk2(wq.x, wq.y), pk2(h.x, h.y), y0);
                y1 = ffma2(pk2(wq.z, wq.w), pk2(h.z, h.w), y1);
            }
            float2 f0 = upk2(y0), f1 = upk2(y1);
            float y = bo + (f0.x + f1.x) + (f0.y + f1.y);
            err = 0.9f * err + 0.1f * (x[7] - y);
            if (t == 0) out[s] = y;
        }
        // no trailing barrier: next S1 writes sg (no pending readers) and reads
        // sh1 (stable since S2) / xbuf (barrier-protected at restage)
    }
}

extern "C" void kernel_launch(void* const* d_in, const int* in_sizes, int n_in,
                              void* d_out, int out_size) {
    const int T = in_sizes[0] / INP;
    lstm_r5_kernel<<<1, NTHREADS>>>(
        (const float*)d_in[0],
        (const float*)d_in[1], (const float*)d_in[2],
        (const float*)d_in[3], (const float*)d_in[4],
        (const float*)d_in[5], (const float*)d_in[6],
        (const float*)d_in[7], (const float*)d_in[8],
        (const float*)d_in[9], (const float*)d_in[10],
        (float*)d_out, T);
}